// round 14
// baseline (speedup 1.0000x reference)
#include <cuda_runtime.h>
#include <cuda_fp16.h>
#include <math.h>

typedef unsigned int u32;

// Problem constants
#define BB 2
#define SS 2048
#define DD 1024
#define HH 16
#define DFFN 4096
#define MROWS (BB*SS)          // 4096
#define NQKV 3072
#define RES_SCALE 0.70710678118654752440f

// ---------------- device scratch ----------------
__device__ __half g_h   [MROWS * DD];
__device__ __half g_qkv [MROWS * NQKV];
__device__ __half g_ctx [MROWS * DD];
__device__ float  g_x1  [MROWS * DD];
__device__ __half g_ff  [MROWS * DFFN];
__device__ __half g_wqkv[NQKV * DD];
__device__ __half g_wo  [DD * DD];
__device__ __half g_w1  [DFFN * DD];
__device__ __half g_w2  [DD * DFFN];
__device__ float  g_bqkv[NQKV];

// ---------------- fused convert + LN1 (one launch) ----------------
__global__ __launch_bounds__(256) void cvt_all_kernel(
    const float* __restrict__ Wq, const float* __restrict__ Wk,
    const float* __restrict__ Wv, const float* __restrict__ Wo,
    const float* __restrict__ W1, const float* __restrict__ W2,
    const float* __restrict__ bq, const float* __restrict__ bk,
    const float* __restrict__ bv,
    const float* __restrict__ x,
    const float* __restrict__ ln1g, const float* __restrict__ ln1b)
{
    int bid = blockIdx.x;
    int tx = threadIdx.x, ty = threadIdx.y;
    int tid = ty * 32 + tx;

    if (bid >= 12289) {
        // ---- LN1 row ----
        int row = bid - 12289;
        const float4* xr = (const float4*)(x + (size_t)row * DD);
        float4 v = xr[tid];
        float s  = v.x + v.y + v.z + v.w;
        float ss = v.x*v.x + v.y*v.y + v.z*v.z + v.w*v.w;
        #pragma unroll
        for (int o = 16; o; o >>= 1) {
            s  += __shfl_xor_sync(0xffffffffu, s, o);
            ss += __shfl_xor_sync(0xffffffffu, ss, o);
        }
        __shared__ float sm1[8], sm2[8];
        int w = tid >> 5, l = tid & 31;
        if (l == 0) { sm1[w] = s; sm2[w] = ss; }
        __syncthreads();
        if (tid == 0) {
            float S = 0.f, SSu = 0.f;
            #pragma unroll
            for (int i = 0; i < 8; i++) { S += sm1[i]; SSu += sm2[i]; }
            float mu  = S  * (1.f / DD);
            float var = SSu * (1.f / DD) - mu * mu;
            sm1[0] = mu;
            sm2[0] = rsqrtf(var + 1e-5f);
        }
        __syncthreads();
        float mu  = sm1[0];
        float inv = sm2[0];
        float4 gg = ((const float4*)ln1g)[tid];
        float4 bb = ((const float4*)ln1b)[tid];
        __half2* orow = (__half2*)(g_h + (size_t)row * DD);
        orow[tid * 2 + 0] = __floats2half2_rn((v.x - mu) * inv * gg.x + bb.x,
                                              (v.y - mu) * inv * gg.y + bb.y);
        orow[tid * 2 + 1] = __floats2half2_rn((v.z - mu) * inv * gg.z + bb.z,
                                              (v.w - mu) * inv * gg.w + bb.w);
        return;
    }

    if (bid == 12288) {
        #pragma unroll
        for (int i = 0; i < 4; i++) {
            int j = tid + i * 256;
            g_bqkv[j]          = bq[j];
            g_bqkv[DD + j]     = bk[j];
            g_bqkv[2 * DD + j] = bv[j];
        }
        return;
    }

    const float* in;
    __half* out;
    int Kdim, Ndim, n0, k0, rowOff;
    if (bid < 4096) {
        int m = bid >> 10;
        int lb = bid & 1023;
        Kdim = DD; Ndim = DD;
        n0 = (lb & 31) * 32; k0 = (lb >> 5) * 32;
        if (m == 0)      { in = Wq; out = g_wqkv; rowOff = 0; }
        else if (m == 1) { in = Wk; out = g_wqkv; rowOff = DD; }
        else if (m == 2) { in = Wv; out = g_wqkv; rowOff = 2 * DD; }
        else             { in = Wo; out = g_wo;   rowOff = 0; }
    } else if (bid < 8192) {
        int lb = bid - 4096;
        Kdim = DD; Ndim = DFFN;
        n0 = (lb & 127) * 32; k0 = (lb >> 7) * 32;
        in = W1; out = g_w1; rowOff = 0;
    } else {
        int lb = bid - 8192;
        Kdim = DFFN; Ndim = DD;
        n0 = (lb & 31) * 32; k0 = (lb >> 5) * 32;
        in = W2; out = g_w2; rowOff = 0;
    }

    __shared__ float sm[32][33];
    #pragma unroll
    for (int i = 0; i < 4; i++) {
        int r = ty + i * 8;
        sm[r][tx] = in[(size_t)(k0 + r) * Ndim + n0 + tx];
    }
    __syncthreads();
    #pragma unroll
    for (int i = 0; i < 4; i++) {
        int r = ty + i * 8;
        out[(size_t)(rowOff + n0 + r) * Kdim + k0 + tx] = __float2half_rn(sm[tx][r]);
    }
}

// ---------------- LayerNorm (fp32 in, fp16 out) — used for LN2 ----------------
__global__ __launch_bounds__(256) void ln_kernel(const float* __restrict__ x,
                                                 const float* __restrict__ g,
                                                 const float* __restrict__ b,
                                                 __half* __restrict__ out)
{
    int row = blockIdx.x;
    int tid = threadIdx.x;
    const float4* xr = (const float4*)(x + (size_t)row * DD);
    float4 v = xr[tid];
    float s  = v.x + v.y + v.z + v.w;
    float ss = v.x*v.x + v.y*v.y + v.z*v.z + v.w*v.w;
    #pragma unroll
    for (int o = 16; o; o >>= 1) {
        s  += __shfl_xor_sync(0xffffffffu, s, o);
        ss += __shfl_xor_sync(0xffffffffu, ss, o);
    }
    __shared__ float sm1[8], sm2[8];
    int w = tid >> 5, l = tid & 31;
    if (l == 0) { sm1[w] = s; sm2[w] = ss; }
    __syncthreads();
    if (tid == 0) {
        float S = 0.f, SSu = 0.f;
        #pragma unroll
        for (int i = 0; i < 8; i++) { S += sm1[i]; SSu += sm2[i]; }
        float mu  = S  * (1.f / DD);
        float var = SSu * (1.f / DD) - mu * mu;
        sm1[0] = mu;
        sm2[0] = rsqrtf(var + 1e-5f);
    }
    __syncthreads();
    float mu  = sm1[0];
    float inv = sm2[0];
    float4 gg = ((const float4*)g)[tid];
    float4 bb = ((const float4*)b)[tid];
    __half2* orow = (__half2*)(out + (size_t)row * DD);
    orow[tid * 2 + 0] = __floats2half2_rn((v.x - mu) * inv * gg.x + bb.x,
                                          (v.y - mu) * inv * gg.y + bb.y);
    orow[tid * 2 + 1] = __floats2half2_rn((v.z - mu) * inv * gg.z + bb.z,
                                          (v.w - mu) * inv * gg.w + bb.w);
}

// ---------------- FP16 tensor-core GEMM: 256 thr, 8 warps x (64x32), low regs --------
#define BKH 64
#define TSTRIDE 72
#define OP_STAGE (128 * TSTRIDE)
#define NSTAGE 3
#define STAGE_H (2 * OP_STAGE)
#define SMEM_BYTES (NSTAGE * STAGE_H * 2)        // 110592 B

__device__ __forceinline__ float gelu_tanh(float x) {
    float x3 = x * x * x;
    return 0.5f * x * (1.f + tanhf(0.7978845608028654f * (x + 0.044715f * x3)));
}
__device__ __forceinline__ void cp_async16h(__half* dst, const __half* src) {
    u32 d = (u32)__cvta_generic_to_shared(dst);
    asm volatile("cp.async.cg.shared.global [%0], [%1], 16;\n" :: "r"(d), "l"(src));
}
__device__ __forceinline__ void cp_commit() {
    asm volatile("cp.async.commit_group;\n");
}
__device__ __forceinline__ void cp_wait1() {
    asm volatile("cp.async.wait_group 1;\n" ::: "memory");
}
__device__ __forceinline__ void ldsm4(u32& r0, u32& r1, u32& r2, u32& r3, u32 addr) {
    asm volatile("ldmatrix.sync.aligned.m8n8.x4.shared.b16 {%0,%1,%2,%3}, [%4];"
                 : "=r"(r0), "=r"(r1), "=r"(r2), "=r"(r3) : "r"(addr));
}
__device__ __forceinline__ void ldsm4t(u32& r0, u32& r1, u32& r2, u32& r3, u32 addr) {
    asm volatile("ldmatrix.sync.aligned.m8n8.x4.trans.shared.b16 {%0,%1,%2,%3}, [%4];"
                 : "=r"(r0), "=r"(r1), "=r"(r2), "=r"(r3) : "r"(addr));
}
__device__ __forceinline__ void mma_f16(float* acc,
                                        u32 a0, u32 a1, u32 a2, u32 a3,
                                        u32 b0, u32 b1)
{
    float d0 = acc[0], d1 = acc[1], d2 = acc[2], d3 = acc[3];
    asm volatile(
        "mma.sync.aligned.m16n8k16.row.col.f32.f16.f16.f32 "
        "{%0,%1,%2,%3}, {%4,%5,%6,%7}, {%8,%9}, {%0,%1,%2,%3};"
        : "+f"(d0), "+f"(d1), "+f"(d2), "+f"(d3)
        : "r"(a0), "r"(a1), "r"(a2), "r"(a3), "r"(b0), "r"(b1));
    acc[0] = d0; acc[1] = d1; acc[2] = d2; acc[3] = d3;
}

template<int MODE, int KDIM>
__global__ __launch_bounds__(256, 2)
void mma_gemm(const __half* __restrict__ A, const __half* __restrict__ Bt,
              const float* __restrict__ bias, const float* __restrict__ R,
              void* __restrict__ Cv, int N, float scale)
{
    extern __shared__ __half smem[];
    constexpr int K = KDIM;
    constexpr int T = K / BKH;

    const int tid  = threadIdx.x;
    const int lane = tid & 31;
    const int warp = tid >> 5;            // 0..7
    const int wm   = (warp >> 2) * 64;    // 0 / 64
    const int wn   = (warp & 3) * 32;     // 0,32,64,96
    const int bm   = blockIdx.y * 128;
    const int bn   = blockIdx.x * 128;
    const int gid  = lane >> 2;
    const int tig  = lane & 3;

    const int q = lane >> 3, ri = lane & 7;
    const u32 aoff0 = (u32)(((wm + (q & 1) * 8 + ri) * TSTRIDE + (q >> 1) * 8) * 2);
    const u32 boff0 = (u32)(((wn + (q >> 1) * 8 + ri) * TSTRIDE + (q & 1) * 8) * 2);

    float acc[4][4][4];
    #pragma unroll
    for (int mi = 0; mi < 4; mi++)
        #pragma unroll
        for (int ni = 0; ni < 4; ni++)
            #pragma unroll
            for (int r = 0; r < 4; r++) acc[mi][ni][r] = 0.f;

    // stage loader: per operand 128 rows x 8 chunks(16B) = 1024 chunks, 256 thr -> 4 it
    auto load_tile = [&](int s, int tp) {
        __half* as = smem + s * STAGE_H;
        __half* bs = as + OP_STAGE;
        int k0 = tp * BKH;
        const __half* Ag = A + (size_t)bm * K + k0;
        const __half* Bg = Bt + (size_t)bn * K + k0;
        #pragma unroll
        for (int i = 0; i < 4; i++) {
            int idx = tid + i * 256;
            int r = idx >> 3, c = (idx & 7) * 8;
            cp_async16h(as + r * TSTRIDE + c, Ag + (size_t)r * K + c);
            cp_async16h(bs + r * TSTRIDE + c, Bg + (size_t)r * K + c);
        }
        cp_commit();
    };

    load_tile(0, 0);
    load_tile(1, 1);

    int sc = 0;
    #pragma unroll 1
    for (int t = 0; t < T; t++) {
        cp_wait1();
        __syncthreads();

        if (t + 2 < T) {
            int sp = sc + 2; if (sp >= NSTAGE) sp -= NSTAGE;
            load_tile(sp, t + 2);
        }

        const u32 asAddr = (u32)__cvta_generic_to_shared(smem + sc * STAGE_H);
        const u32 bsAddr = asAddr + (u32)(OP_STAGE * 2);

        #pragma unroll
        for (int kk = 0; kk < 4; kk++) {
            const u32 kb = (u32)(kk * 32);
            u32 af[4][4];
            #pragma unroll
            for (int mi = 0; mi < 4; mi++) {
                u32 r0, r1, r2, r3;
                ldsm4(r0, r1, r2, r3, asAddr + aoff0 + (u32)(mi * 16 * TSTRIDE * 2) + kb);
                af[mi][0] = r0; af[mi][1] = r1; af[mi][2] = r2; af[mi][3] = r3;
            }
            u32 bf[4][2];
            #pragma unroll
            for (int np = 0; np < 2; np++) {
                u32 r0, r1, r2, r3;
                ldsm4(r0, r1, r2, r3, bsAddr + boff0 + (u32)(np * 16 * TSTRIDE * 2) + kb);
                bf[np * 2 + 0][0] = r0; bf[np * 2 + 0][1] = r1;
                bf[np * 2 + 1][0] = r2; bf[np * 2 + 1][1] = r3;
            }
            #pragma unroll
            for (int mi = 0; mi < 4; mi++) {
                u32 a0 = af[mi][0], a1 = af[mi][1];
                u32 a2 = af[mi][2], a3 = af[mi][3];
                #pragma unroll
                for (int ni = 0; ni < 4; ni++) {
                    u32 b0 = bf[ni][0], b1 = bf[ni][1];
                    mma_f16(&acc[mi][ni][0], a0, a1, a2, a3, b0, b1);
                }
            }
        }

        if (++sc >= NSTAGE) sc = 0;
    }

    // epilogue: frag (mi,ni): rows bm+wm+mi*16+gid+{0,8}, cols bn+wn+ni*8+tig*2
    const int rbase = bm + wm + gid;
    const int cbase = bn + wn + tig * 2;
    #pragma unroll
    for (int mi = 0; mi < 4; mi++) {
        #pragma unroll
        for (int half_ = 0; half_ < 2; half_++) {
            int r = rbase + mi * 16 + half_ * 8;
            #pragma unroll
            for (int ni = 0; ni < 4; ni++) {
                int c = cbase + ni * 8;
                float v0 = acc[mi][ni][half_ * 2 + 0] + bias[c];
                float v1 = acc[mi][ni][half_ * 2 + 1] + bias[c + 1];
                if (MODE == 0) {
                    __half2* C = (__half2*)((__half*)Cv + (size_t)r * N + c);
                    *C = __floats2half2_rn(v0, v1);
                } else if (MODE == 1) {
                    __half2* C = (__half2*)((__half*)Cv + (size_t)r * N + c);
                    *C = __floats2half2_rn(gelu_tanh(v0), gelu_tanh(v1));
                } else {
                    float* C = (float*)Cv + (size_t)r * N + c;
                    const float2 rr = *(const float2*)(R + (size_t)r * N + c);
                    float2 o2;
                    o2.x = rr.x + v0 * scale;
                    o2.y = rr.y + v1 * scale;
                    *(float2*)C = o2;
                }
            }
        }
    }
}

// ---------------- tensor-core block-local causal attention ----------------
// V kept in [key][d] layout (same fill as K); PV B-fragments via ldmatrix.trans.
__global__ __launch_bounds__(128)
void attn_kernel(const __half* __restrict__ qkv, __half* __restrict__ ctx)
{
    __shared__ __half qs[64 * TSTRIDE];
    __shared__ __half ks[64 * TSTRIDE];
    __shared__ __half vs[64 * TSTRIDE];

    const int tid  = threadIdx.x;
    const int lane = tid & 31;
    const int warp = tid >> 5;
    const int gid  = lane >> 2;
    const int tig  = lane & 3;
    const int rowbase = blockIdx.z * SS + blockIdx.x * 64;
    const int colbase = blockIdx.y * 64;

    #pragma unroll
    for (int i = 0; i < 4; i++) {
        int idx = tid + i * 128;
        int r = idx >> 3, c = (idx & 7) * 8;
        size_t base = (size_t)(rowbase + r) * NQKV + colbase + c;
        *(uint4*)(qs + r * TSTRIDE + c) = *(const uint4*)(qkv + base);
        *(uint4*)(ks + r * TSTRIDE + c) = *(const uint4*)(qkv + base + DD);
        *(uint4*)(vs + r * TSTRIDE + c) = *(const uint4*)(qkv + base + 2 * DD);
    }
    __syncthreads();

    const int q = lane >> 3, ri = lane & 7;
    const u32 qsA = (u32)__cvta_generic_to_shared(qs);
    const u32 ksA = (u32)__cvta_generic_to_shared(ks);
    const u32 vsA = (u32)__cvta_generic_to_shared(vs);
    const u32 aoff0 = (u32)(((warp * 16 + (q & 1) * 8 + ri) * TSTRIDE + (q >> 1) * 8) * 2);
    const u32 boff0 = (u32)((((q >> 1) * 8 + ri) * TSTRIDE + (q & 1) * 8) * 2);
    const u32 voff0 = (u32)((((q & 1) * 8 + ri) * TSTRIDE + (q >> 1) * 8) * 2);

    float sacc[8][4];
    #pragma unroll
    for (int ni = 0; ni < 8; ni++)
        #pragma unroll
        for (int r = 0; r < 4; r++) sacc[ni][r] = 0.f;

    #pragma unroll
    for (int j = 0; j < 4; j++) {
        const u32 kb = (u32)(j * 32);
        u32 a0, a1, a2, a3;
        ldsm4(a0, a1, a2, a3, qsA + aoff0 + kb);
        u32 bfrag[8][2];
        #pragma unroll
        for (int np = 0; np < 4; np++) {
            u32 r0, r1, r2, r3;
            ldsm4(r0, r1, r2, r3, ksA + boff0 + (u32)(np * 16 * TSTRIDE * 2) + kb);
            bfrag[np * 2 + 0][0] = r0; bfrag[np * 2 + 0][1] = r1;
            bfrag[np * 2 + 1][0] = r2; bfrag[np * 2 + 1][1] = r3;
        }
        #pragma unroll
        for (int ni = 0; ni < 8; ni++)
            mma_f16(&sacc[ni][0], a0, a1, a2, a3, bfrag[ni][0], bfrag[ni][1]);
    }

    const int rowA = warp * 16 + gid;
    const int rowB = rowA + 8;
    float mA = -1e30f, mB = -1e30f;
    #pragma unroll
    for (int ni = 0; ni < 8; ni++) {
        int c0 = ni * 8 + tig * 2, c1 = c0 + 1;
        float s0 = sacc[ni][0] * 0.125f;
        float s1 = sacc[ni][1] * 0.125f;
        float s2 = sacc[ni][2] * 0.125f;
        float s3 = sacc[ni][3] * 0.125f;
        sacc[ni][0] = s0; sacc[ni][1] = s1; sacc[ni][2] = s2; sacc[ni][3] = s3;
        if (c0 <= rowA) mA = fmaxf(mA, s0);
        if (c1 <= rowA) mA = fmaxf(mA, s1);
        if (c0 <= rowB) mB = fmaxf(mB, s2);
        if (c1 <= rowB) mB = fmaxf(mB, s3);
    }
    mA = fmaxf(mA, __shfl_xor_sync(0xffffffffu, mA, 1));
    mA = fmaxf(mA, __shfl_xor_sync(0xffffffffu, mA, 2));
    mB = fmaxf(mB, __shfl_xor_sync(0xffffffffu, mB, 1));
    mB = fmaxf(mB, __shfl_xor_sync(0xffffffffu, mB, 2));

    float sumA = 0.f, sumB = 0.f;
    #pragma unroll
    for (int ni = 0; ni < 8; ni++) {
        int c0 = ni * 8 + tig * 2, c1 = c0 + 1;
        float e0 = (c0 <= rowA) ? expf(sacc[ni][0] - mA) : 0.f;
        float e1 = (c1 <= rowA) ? expf(sacc[ni][1] - mA) : 0.f;
        float e2 = (c0 <= rowB) ? expf(sacc[ni][2] - mB) : 0.f;
        float e3 = (c1 <= rowB) ? expf(sacc[ni][3] - mB) : 0.f;
        sacc[ni][0] = e0; sacc[ni][1] = e1; sacc[ni][2] = e2; sacc[ni][3] = e3;
        sumA += e0 + e1;
        sumB += e2 + e3;
    }
    sumA += __shfl_xor_sync(0xffffffffu, sumA, 1);
    sumA += __shfl_xor_sync(0xffffffffu, sumA, 2);
    sumB += __shfl_xor_sync(0xffffffffu, sumB, 1);
    sumB += __shfl_xor_sync(0xffffffffu, sumB, 2);
    const float invA = 1.f / sumA, invB = 1.f / sumB;

    u32 ph[8][2];
    #pragma unroll
    for (int ni = 0; ni < 8; ni++) {
        __half2 lo = __floats2half2_rn(sacc[ni][0] * invA, sacc[ni][1] * invA);
        __half2 hi = __floats2half2_rn(sacc[ni][2] * invB, sacc[ni][3] * invB);
        ph[ni][0] = *(u32*)&lo;
        ph[ni][1] = *(u32*)&hi;
    }

    float oacc[8][4];
    #pragma unroll
    for (int ni = 0; ni < 8; ni++)
        #pragma unroll
        for (int r = 0; r < 4; r++) oacc[ni][r] = 0.f;

    #pragma unroll
    for (int j = 0; j < 4; j++) {
        u32 a0 = ph[2 * j][0], a1 = ph[2 * j][1];
        u32 a2 = ph[2 * j + 1][0], a3 = ph[2 * j + 1][1];
        u32 bfrag[8][2];
        #pragma unroll
        for (int np = 0; np < 4; np++) {
            u32 r0, r1, r2, r3;
            ldsm4t(r0, r1, r2, r3,
                   vsA + voff0 + (u32)((j * 16 * TSTRIDE + np * 16) * 2));
            bfrag[np * 2 + 0][0] = r0; bfrag[np * 2 + 0][1] = r1;
            bfrag[np * 2 + 1][0] = r2; bfrag[np * 2 + 1][1] = r3;
        }
        #pragma unroll
        for (int ni = 0; ni < 8; ni++)
            mma_f16(&oacc[ni][0], a0, a1, a2, a3, bfrag[ni][0], bfrag[ni][1]);
    }

    __half* dA = ctx + (size_t)(rowbase + rowA) * DD + colbase + tig * 2;
    __half* dB = ctx + (size_t)(rowbase + rowB) * DD + colbase + tig * 2;
    #pragma unroll
    for (int ni = 0; ni < 8; ni++) {
        *(__half2*)(dA + ni * 8) = __floats2half2_rn(oacc[ni][0], oacc[ni][1]);
        *(__half2*)(dB + ni * 8) = __floats2half2_rn(oacc[ni][2], oacc[ni][3]);
    }
}

// ---------------- launch ----------------
extern "C" void kernel_launch(void* const* d_in, const int* in_sizes, int n_in,
                              void* d_out, int out_size)
{
    const float* x    = (const float*)d_in[0];
    const float* Wq   = (const float*)d_in[2];
    const float* bq   = (const float*)d_in[3];
    const float* Wk   = (const float*)d_in[4];
    const float* bk   = (const float*)d_in[5];
    const float* Wv   = (const float*)d_in[6];
    const float* bv   = (const float*)d_in[7];
    const float* Wo   = (const float*)d_in[8];
    const float* bo   = (const float*)d_in[9];
    const float* ln1g = (const float*)d_in[10];
    const float* ln1b = (const float*)d_in[11];
    const float* ln2g = (const float*)d_in[12];
    const float* ln2b = (const float*)d_in[13];
    const float* W1   = (const float*)d_in[14];
    const float* b1   = (const float*)d_in[15];
    const float* W2   = (const float*)d_in[16];
    const float* b2   = (const float*)d_in[17];
    float* out = (float*)d_out;

    __half *h, *qkv, *ctx, *ff;
    float *x1, *bqkv;
    __half *wqkv, *wo, *w1, *w2;
    cudaGetSymbolAddress((void**)&h,    g_h);
    cudaGetSymbolAddress((void**)&qkv,  g_qkv);
    cudaGetSymbolAddress((void**)&ctx,  g_ctx);
    cudaGetSymbolAddress((void**)&x1,   g_x1);
    cudaGetSymbolAddress((void**)&ff,   g_ff);
    cudaGetSymbolAddress((void**)&wqkv, g_wqkv);
    cudaGetSymbolAddress((void**)&wo,   g_wo);
    cudaGetSymbolAddress((void**)&w1,   g_w1);
    cudaGetSymbolAddress((void**)&w2,   g_w2);
    cudaGetSymbolAddress((void**)&bqkv, g_bqkv);

    cudaFuncSetAttribute((const void*)mma_gemm<0, DD>,
                         cudaFuncAttributeMaxDynamicSharedMemorySize, SMEM_BYTES);
    cudaFuncSetAttribute((const void*)mma_gemm<2, DD>,
                         cudaFuncAttributeMaxDynamicSharedMemorySize, SMEM_BYTES);
    cudaFuncSetAttribute((const void*)mma_gemm<1, DD>,
                         cudaFuncAttributeMaxDynamicSharedMemorySize, SMEM_BYTES);
    cudaFuncSetAttribute((const void*)mma_gemm<2, DFFN>,
                         cudaFuncAttributeMaxDynamicSharedMemorySize, SMEM_BYTES);

    // 0+1. fused convert + LN1 (one launch)
    cvt_all_kernel<<<12289 + MROWS, dim3(32, 8)>>>(Wq, Wk, Wv, Wo, W1, W2,
                                                   bq, bk, bv, x, ln1g, ln1b);

    // 2. fused QKV projection (K=1024)
    dim3 gQKV(NQKV / 128, MROWS / 128);
    mma_gemm<0, DD><<<gQKV, 256, SMEM_BYTES>>>(h, wqkv, bqkv, nullptr, qkv, NQKV, 0.f);

    // 3. tensor-core attention -> ctx (half)
    dim3 gA(SS / 64, HH, BB);
    attn_kernel<<<gA, 128>>>(qkv, ctx);

    // 4. x1 = x + (ctx @ Wo + bo) * res_scale   (K=1024)
    dim3 gD(DD / 128, MROWS / 128);
    mma_gemm<2, DD><<<gD, 256, SMEM_BYTES>>>(ctx, wo, bo, x, x1, DD, RES_SCALE);

    // 5. LN2 -> h (half)
    ln_kernel<<<MROWS, 256>>>(x1, ln2g, ln2b, h);

    // 6. ff = (half)gelu(h @ W1 + b1)   (K=1024)
    dim3 gF1(DFFN / 128, MROWS / 128);
    mma_gemm<1, DD><<<gF1, 256, SMEM_BYTES>>>(h, w1, b1, nullptr, ff, DFFN, 0.f);

    // 7. out = x1 + (ff @ W2 + b2) * res_scale   (K=4096)
    mma_gemm<2, DFFN><<<gD, 256, SMEM_BYTES>>>(ff, w2, b2, x1, out, DD, RES_SCALE);
}

// round 15
// speedup vs baseline: 1.0222x; 1.0222x over previous
#include <cuda_runtime.h>
#include <cuda_fp16.h>
#include <math.h>

typedef unsigned int u32;

// Problem constants
#define BB 2
#define SS 2048
#define DD 1024
#define HH 16
#define DFFN 4096
#define MROWS (BB*SS)          // 4096
#define NQKV 3072
#define RES_SCALE 0.70710678118654752440f

// ---------------- device scratch ----------------
__device__ __half g_h   [MROWS * DD];
__device__ __half g_qkv [MROWS * NQKV];
__device__ __half g_ctx [MROWS * DD];
__device__ float  g_x1  [MROWS * DD];
__device__ __half g_ff  [MROWS * DFFN];
__device__ __half g_wqkv[NQKV * DD];
__device__ __half g_wo  [DD * DD];
__device__ __half g_w1  [DFFN * DD];
__device__ __half g_w2  [DD * DFFN];
__device__ float  g_bqkv[NQKV];

// ---------------- convert A: Wq/Wk/Wv + bias + LN1 (feeds QKV GEMM) ----------------
// bids [0,3072): Wq/Wk/Wv tiles; 3072: bias concat; [3073, 3073+4096): LN1 rows
__global__ __launch_bounds__(256) void cvtA_kernel(
    const float* __restrict__ Wq, const float* __restrict__ Wk,
    const float* __restrict__ Wv,
    const float* __restrict__ bq, const float* __restrict__ bk,
    const float* __restrict__ bv,
    const float* __restrict__ x,
    const float* __restrict__ ln1g, const float* __restrict__ ln1b)
{
    int bid = blockIdx.x;
    int tx = threadIdx.x, ty = threadIdx.y;
    int tid = ty * 32 + tx;

    if (bid >= 3073) {
        // ---- LN1 row ----
        int row = bid - 3073;
        const float4* xr = (const float4*)(x + (size_t)row * DD);
        float4 v = xr[tid];
        float s  = v.x + v.y + v.z + v.w;
        float ss = v.x*v.x + v.y*v.y + v.z*v.z + v.w*v.w;
        #pragma unroll
        for (int o = 16; o; o >>= 1) {
            s  += __shfl_xor_sync(0xffffffffu, s, o);
            ss += __shfl_xor_sync(0xffffffffu, ss, o);
        }
        __shared__ float sm1[8], sm2[8];
        int w = tid >> 5, l = tid & 31;
        if (l == 0) { sm1[w] = s; sm2[w] = ss; }
        __syncthreads();
        if (tid == 0) {
            float S = 0.f, SSu = 0.f;
            #pragma unroll
            for (int i = 0; i < 8; i++) { S += sm1[i]; SSu += sm2[i]; }
            float mu  = S  * (1.f / DD);
            float var = SSu * (1.f / DD) - mu * mu;
            sm1[0] = mu;
            sm2[0] = rsqrtf(var + 1e-5f);
        }
        __syncthreads();
        float mu  = sm1[0];
        float inv = sm2[0];
        float4 gg = ((const float4*)ln1g)[tid];
        float4 bb = ((const float4*)ln1b)[tid];
        __half2* orow = (__half2*)(g_h + (size_t)row * DD);
        orow[tid * 2 + 0] = __floats2half2_rn((v.x - mu) * inv * gg.x + bb.x,
                                              (v.y - mu) * inv * gg.y + bb.y);
        orow[tid * 2 + 1] = __floats2half2_rn((v.z - mu) * inv * gg.z + bb.z,
                                              (v.w - mu) * inv * gg.w + bb.w);
        return;
    }

    if (bid == 3072) {
        #pragma unroll
        for (int i = 0; i < 4; i++) {
            int j = tid + i * 256;
            g_bqkv[j]          = bq[j];
            g_bqkv[DD + j]     = bk[j];
            g_bqkv[2 * DD + j] = bv[j];
        }
        return;
    }

    // Wq / Wk / Wv transpose-convert into g_wqkv
    int m = bid >> 10;                // 0,1,2
    int lb = bid & 1023;
    int n0 = (lb & 31) * 32, k0 = (lb >> 5) * 32;
    const float* in = (m == 0) ? Wq : (m == 1) ? Wk : Wv;
    int rowOff = m * DD;

    __shared__ float sm[32][33];
    #pragma unroll
    for (int i = 0; i < 4; i++) {
        int r = ty + i * 8;
        sm[r][tx] = in[(size_t)(k0 + r) * DD + n0 + tx];
    }
    __syncthreads();
    #pragma unroll
    for (int i = 0; i < 4; i++) {
        int r = ty + i * 8;
        g_wqkv[(size_t)(rowOff + n0 + r) * DD + k0 + tx] = __float2half_rn(sm[tx][r]);
    }
}

// ---------------- convert B: Wo / W1 / W2 (independent; runs on side stream) ---------
// bids [0,1024): Wo; [1024,5120): W1; [5120,9216): W2
__global__ __launch_bounds__(256) void cvtB_kernel(
    const float* __restrict__ Wo, const float* __restrict__ W1,
    const float* __restrict__ W2)
{
    int bid = blockIdx.x;
    int tx = threadIdx.x, ty = threadIdx.y;

    const float* in;
    __half* out;
    int Kdim, Ndim, n0, k0;
    if (bid < 1024) {
        Kdim = DD; Ndim = DD;
        n0 = (bid & 31) * 32; k0 = (bid >> 5) * 32;
        in = Wo; out = g_wo;
    } else if (bid < 5120) {
        int lb = bid - 1024;
        Kdim = DD; Ndim = DFFN;
        n0 = (lb & 127) * 32; k0 = (lb >> 7) * 32;
        in = W1; out = g_w1;
    } else {
        int lb = bid - 5120;
        Kdim = DFFN; Ndim = DD;
        n0 = (lb & 31) * 32; k0 = (lb >> 5) * 32;
        in = W2; out = g_w2;
    }

    __shared__ float sm[32][33];
    #pragma unroll
    for (int i = 0; i < 4; i++) {
        int r = ty + i * 8;
        sm[r][tx] = in[(size_t)(k0 + r) * Ndim + n0 + tx];
    }
    __syncthreads();
    #pragma unroll
    for (int i = 0; i < 4; i++) {
        int r = ty + i * 8;
        out[(size_t)(n0 + r) * Kdim + k0 + tx] = __float2half_rn(sm[tx][r]);
    }
}

// ---------------- LayerNorm (fp32 in, fp16 out) — LN2 ----------------
__global__ __launch_bounds__(256) void ln_kernel(const float* __restrict__ x,
                                                 const float* __restrict__ g,
                                                 const float* __restrict__ b,
                                                 __half* __restrict__ out)
{
    int row = blockIdx.x;
    int tid = threadIdx.x;
    const float4* xr = (const float4*)(x + (size_t)row * DD);
    float4 v = xr[tid];
    float s  = v.x + v.y + v.z + v.w;
    float ss = v.x*v.x + v.y*v.y + v.z*v.z + v.w*v.w;
    #pragma unroll
    for (int o = 16; o; o >>= 1) {
        s  += __shfl_xor_sync(0xffffffffu, s, o);
        ss += __shfl_xor_sync(0xffffffffu, ss, o);
    }
    __shared__ float sm1[8], sm2[8];
    int w = tid >> 5, l = tid & 31;
    if (l == 0) { sm1[w] = s; sm2[w] = ss; }
    __syncthreads();
    if (tid == 0) {
        float S = 0.f, SSu = 0.f;
        #pragma unroll
        for (int i = 0; i < 8; i++) { S += sm1[i]; SSu += sm2[i]; }
        float mu  = S  * (1.f / DD);
        float var = SSu * (1.f / DD) - mu * mu;
        sm1[0] = mu;
        sm2[0] = rsqrtf(var + 1e-5f);
    }
    __syncthreads();
    float mu  = sm1[0];
    float inv = sm2[0];
    float4 gg = ((const float4*)g)[tid];
    float4 bb = ((const float4*)b)[tid];
    __half2* orow = (__half2*)(out + (size_t)row * DD);
    orow[tid * 2 + 0] = __floats2half2_rn((v.x - mu) * inv * gg.x + bb.x,
                                          (v.y - mu) * inv * gg.y + bb.y);
    orow[tid * 2 + 1] = __floats2half2_rn((v.z - mu) * inv * gg.z + bb.z,
                                          (v.w - mu) * inv * gg.w + bb.w);
}

// ---------------- FP16 tensor-core GEMM (R12 config: 128 thr, 64x64 warp tiles) ------
#define BKH 64
#define TSTRIDE 72
#define OP_STAGE (128 * TSTRIDE)
#define NSTAGE 3
#define STAGE_H (2 * OP_STAGE)
#define SMEM_BYTES (NSTAGE * STAGE_H * 2)        // 110592 B

__device__ __forceinline__ float gelu_tanh(float x) {
    float x3 = x * x * x;
    return 0.5f * x * (1.f + tanhf(0.7978845608028654f * (x + 0.044715f * x3)));
}
__device__ __forceinline__ void cp_async16h(__half* dst, const __half* src) {
    u32 d = (u32)__cvta_generic_to_shared(dst);
    asm volatile("cp.async.cg.shared.global [%0], [%1], 16;\n" :: "r"(d), "l"(src));
}
__device__ __forceinline__ void cp_commit() {
    asm volatile("cp.async.commit_group;\n");
}
__device__ __forceinline__ void cp_wait1() {
    asm volatile("cp.async.wait_group 1;\n" ::: "memory");
}
__device__ __forceinline__ void ldsm4(u32& r0, u32& r1, u32& r2, u32& r3, u32 addr) {
    asm volatile("ldmatrix.sync.aligned.m8n8.x4.shared.b16 {%0,%1,%2,%3}, [%4];"
                 : "=r"(r0), "=r"(r1), "=r"(r2), "=r"(r3) : "r"(addr));
}
__device__ __forceinline__ void ldsm4t(u32& r0, u32& r1, u32& r2, u32& r3, u32 addr) {
    asm volatile("ldmatrix.sync.aligned.m8n8.x4.trans.shared.b16 {%0,%1,%2,%3}, [%4];"
                 : "=r"(r0), "=r"(r1), "=r"(r2), "=r"(r3) : "r"(addr));
}
__device__ __forceinline__ void mma_f16(float* acc,
                                        u32 a0, u32 a1, u32 a2, u32 a3,
                                        u32 b0, u32 b1)
{
    float d0 = acc[0], d1 = acc[1], d2 = acc[2], d3 = acc[3];
    asm volatile(
        "mma.sync.aligned.m16n8k16.row.col.f32.f16.f16.f32 "
        "{%0,%1,%2,%3}, {%4,%5,%6,%7}, {%8,%9}, {%0,%1,%2,%3};"
        : "+f"(d0), "+f"(d1), "+f"(d2), "+f"(d3)
        : "r"(a0), "r"(a1), "r"(a2), "r"(a3), "r"(b0), "r"(b1));
    acc[0] = d0; acc[1] = d1; acc[2] = d2; acc[3] = d3;
}

template<int MODE, int KDIM>
__global__ __launch_bounds__(128, 2)
void mma_gemm(const __half* __restrict__ A, const __half* __restrict__ Bt,
              const float* __restrict__ bias, const float* __restrict__ R,
              void* __restrict__ Cv, int N, float scale)
{
    extern __shared__ __half smem[];
    constexpr int K = KDIM;
    constexpr int T = K / BKH;

    const int tid  = threadIdx.x;
    const int lane = tid & 31;
    const int warp = tid >> 5;
    const int wm   = (warp >> 1) * 64;
    const int wn   = (warp & 1) * 64;
    const int bm   = blockIdx.y * 128;
    const int bn   = blockIdx.x * 128;
    const int gid  = lane >> 2;
    const int tig  = lane & 3;

    const int q = lane >> 3, ri = lane & 7;
    const u32 aoff0 = (u32)(((wm + (q & 1) * 8 + ri) * TSTRIDE + (q >> 1) * 8) * 2);
    const u32 boff0 = (u32)(((wn + (q >> 1) * 8 + ri) * TSTRIDE + (q & 1) * 8) * 2);

    float acc[4][8][4];
    #pragma unroll
    for (int mi = 0; mi < 4; mi++)
        #pragma unroll
        for (int ni = 0; ni < 8; ni++)
            #pragma unroll
            for (int r = 0; r < 4; r++) acc[mi][ni][r] = 0.f;

    auto load_tile = [&](int s, int tp) {
        __half* as = smem + s * STAGE_H;
        __half* bs = as + OP_STAGE;
        int k0 = tp * BKH;
        const __half* Ag = A + (size_t)bm * K + k0;
        const __half* Bg = Bt + (size_t)bn * K + k0;
        #pragma unroll
        for (int i = 0; i < 8; i++) {
            int idx = tid + i * 128;
            int r = idx >> 3, c = (idx & 7) * 8;
            cp_async16h(as + r * TSTRIDE + c, Ag + (size_t)r * K + c);
            cp_async16h(bs + r * TSTRIDE + c, Bg + (size_t)r * K + c);
        }
        cp_commit();
    };

    load_tile(0, 0);
    load_tile(1, 1);

    int sc = 0;
    #pragma unroll 2
    for (int t = 0; t < T; t++) {
        cp_wait1();
        __syncthreads();

        if (t + 2 < T) {
            int sp = sc + 2; if (sp >= NSTAGE) sp -= NSTAGE;
            load_tile(sp, t + 2);
        }

        const u32 asAddr = (u32)__cvta_generic_to_shared(smem + sc * STAGE_H);
        const u32 bsAddr = asAddr + (u32)(OP_STAGE * 2);

        u32 af[2][4][4];
        u32 bf[2][8][2];

        #pragma unroll
        for (int mi = 0; mi < 4; mi++) {
            u32 r0, r1, r2, r3;
            ldsm4(r0, r1, r2, r3, asAddr + aoff0 + (u32)(mi * 16 * TSTRIDE * 2));
            af[0][mi][0] = r0; af[0][mi][1] = r1; af[0][mi][2] = r2; af[0][mi][3] = r3;
        }
        #pragma unroll
        for (int np = 0; np < 4; np++) {
            u32 r0, r1, r2, r3;
            ldsm4(r0, r1, r2, r3, bsAddr + boff0 + (u32)(np * 16 * TSTRIDE * 2));
            bf[0][np * 2 + 0][0] = r0; bf[0][np * 2 + 0][1] = r1;
            bf[0][np * 2 + 1][0] = r2; bf[0][np * 2 + 1][1] = r3;
        }

        #pragma unroll
        for (int kk = 0; kk < 4; kk++) {
            const int cb = kk & 1, nb = cb ^ 1;
            if (kk < 3) {
                const u32 kb = (u32)((kk + 1) * 32);
                #pragma unroll
                for (int mi = 0; mi < 4; mi++) {
                    u32 r0, r1, r2, r3;
                    ldsm4(r0, r1, r2, r3, asAddr + aoff0 + (u32)(mi * 16 * TSTRIDE * 2) + kb);
                    af[nb][mi][0] = r0; af[nb][mi][1] = r1;
                    af[nb][mi][2] = r2; af[nb][mi][3] = r3;
                }
                #pragma unroll
                for (int np = 0; np < 4; np++) {
                    u32 r0, r1, r2, r3;
                    ldsm4(r0, r1, r2, r3, bsAddr + boff0 + (u32)(np * 16 * TSTRIDE * 2) + kb);
                    bf[nb][np * 2 + 0][0] = r0; bf[nb][np * 2 + 0][1] = r1;
                    bf[nb][np * 2 + 1][0] = r2; bf[nb][np * 2 + 1][1] = r3;
                }
            }
            #pragma unroll
            for (int mi = 0; mi < 4; mi++) {
                u32 a0 = af[cb][mi][0], a1 = af[cb][mi][1];
                u32 a2 = af[cb][mi][2], a3 = af[cb][mi][3];
                #pragma unroll
                for (int ni = 0; ni < 8; ni++) {
                    u32 b0 = bf[cb][ni][0], b1 = bf[cb][ni][1];
                    mma_f16(&acc[mi][ni][0], a0, a1, a2, a3, b0, b1);
                }
            }
        }

        if (++sc >= NSTAGE) sc = 0;
    }

    const int rbase = bm + wm + gid;
    const int cbase = bn + wn + tig * 2;
    #pragma unroll
    for (int mi = 0; mi < 4; mi++) {
        #pragma unroll
        for (int half_ = 0; half_ < 2; half_++) {
            int r = rbase + mi * 16 + half_ * 8;
            #pragma unroll
            for (int ni = 0; ni < 8; ni++) {
                int c = cbase + ni * 8;
                float v0 = acc[mi][ni][half_ * 2 + 0] + bias[c];
                float v1 = acc[mi][ni][half_ * 2 + 1] + bias[c + 1];
                if (MODE == 0) {
                    __half2* C = (__half2*)((__half*)Cv + (size_t)r * N + c);
                    *C = __floats2half2_rn(v0, v1);
                } else if (MODE == 1) {
                    __half2* C = (__half2*)((__half*)Cv + (size_t)r * N + c);
                    *C = __floats2half2_rn(gelu_tanh(v0), gelu_tanh(v1));
                } else {
                    float* C = (float*)Cv + (size_t)r * N + c;
                    const float2 rr = *(const float2*)(R + (size_t)r * N + c);
                    float2 o2;
                    o2.x = rr.x + v0 * scale;
                    o2.y = rr.y + v1 * scale;
                    *(float2*)C = o2;
                }
            }
        }
    }
}

// ---------------- tensor-core block-local causal attention ----------------
__global__ __launch_bounds__(128)
void attn_kernel(const __half* __restrict__ qkv, __half* __restrict__ ctx)
{
    __shared__ __half qs[64 * TSTRIDE];
    __shared__ __half ks[64 * TSTRIDE];
    __shared__ __half vs[64 * TSTRIDE];

    const int tid  = threadIdx.x;
    const int lane = tid & 31;
    const int warp = tid >> 5;
    const int gid  = lane >> 2;
    const int tig  = lane & 3;
    const int rowbase = blockIdx.z * SS + blockIdx.x * 64;
    const int colbase = blockIdx.y * 64;

    #pragma unroll
    for (int i = 0; i < 4; i++) {
        int idx = tid + i * 128;
        int r = idx >> 3, c = (idx & 7) * 8;
        size_t base = (size_t)(rowbase + r) * NQKV + colbase + c;
        *(uint4*)(qs + r * TSTRIDE + c) = *(const uint4*)(qkv + base);
        *(uint4*)(ks + r * TSTRIDE + c) = *(const uint4*)(qkv + base + DD);
        *(uint4*)(vs + r * TSTRIDE + c) = *(const uint4*)(qkv + base + 2 * DD);
    }
    __syncthreads();

    const int q = lane >> 3, ri = lane & 7;
    const u32 qsA = (u32)__cvta_generic_to_shared(qs);
    const u32 ksA = (u32)__cvta_generic_to_shared(ks);
    const u32 vsA = (u32)__cvta_generic_to_shared(vs);
    const u32 aoff0 = (u32)(((warp * 16 + (q & 1) * 8 + ri) * TSTRIDE + (q >> 1) * 8) * 2);
    const u32 boff0 = (u32)((((q >> 1) * 8 + ri) * TSTRIDE + (q & 1) * 8) * 2);
    const u32 voff0 = (u32)((((q & 1) * 8 + ri) * TSTRIDE + (q >> 1) * 8) * 2);

    float sacc[8][4];
    #pragma unroll
    for (int ni = 0; ni < 8; ni++)
        #pragma unroll
        for (int r = 0; r < 4; r++) sacc[ni][r] = 0.f;

    #pragma unroll
    for (int j = 0; j < 4; j++) {
        const u32 kb = (u32)(j * 32);
        u32 a0, a1, a2, a3;
        ldsm4(a0, a1, a2, a3, qsA + aoff0 + kb);
        u32 bfrag[8][2];
        #pragma unroll
        for (int np = 0; np < 4; np++) {
            u32 r0, r1, r2, r3;
            ldsm4(r0, r1, r2, r3, ksA + boff0 + (u32)(np * 16 * TSTRIDE * 2) + kb);
            bfrag[np * 2 + 0][0] = r0; bfrag[np * 2 + 0][1] = r1;
            bfrag[np * 2 + 1][0] = r2; bfrag[np * 2 + 1][1] = r3;
        }
        #pragma unroll
        for (int ni = 0; ni < 8; ni++)
            mma_f16(&sacc[ni][0], a0, a1, a2, a3, bfrag[ni][0], bfrag[ni][1]);
    }

    const int rowA = warp * 16 + gid;
    const int rowB = rowA + 8;
    float mA = -1e30f, mB = -1e30f;
    #pragma unroll
    for (int ni = 0; ni < 8; ni++) {
        int c0 = ni * 8 + tig * 2, c1 = c0 + 1;
        float s0 = sacc[ni][0] * 0.125f;
        float s1 = sacc[ni][1] * 0.125f;
        float s2 = sacc[ni][2] * 0.125f;
        float s3 = sacc[ni][3] * 0.125f;
        sacc[ni][0] = s0; sacc[ni][1] = s1; sacc[ni][2] = s2; sacc[ni][3] = s3;
        if (c0 <= rowA) mA = fmaxf(mA, s0);
        if (c1 <= rowA) mA = fmaxf(mA, s1);
        if (c0 <= rowB) mB = fmaxf(mB, s2);
        if (c1 <= rowB) mB = fmaxf(mB, s3);
    }
    mA = fmaxf(mA, __shfl_xor_sync(0xffffffffu, mA, 1));
    mA = fmaxf(mA, __shfl_xor_sync(0xffffffffu, mA, 2));
    mB = fmaxf(mB, __shfl_xor_sync(0xffffffffu, mB, 1));
    mB = fmaxf(mB, __shfl_xor_sync(0xffffffffu, mB, 2));

    float sumA = 0.f, sumB = 0.f;
    #pragma unroll
    for (int ni = 0; ni < 8; ni++) {
        int c0 = ni * 8 + tig * 2, c1 = c0 + 1;
        float e0 = (c0 <= rowA) ? expf(sacc[ni][0] - mA) : 0.f;
        float e1 = (c1 <= rowA) ? expf(sacc[ni][1] - mA) : 0.f;
        float e2 = (c0 <= rowB) ? expf(sacc[ni][2] - mB) : 0.f;
        float e3 = (c1 <= rowB) ? expf(sacc[ni][3] - mB) : 0.f;
        sacc[ni][0] = e0; sacc[ni][1] = e1; sacc[ni][2] = e2; sacc[ni][3] = e3;
        sumA += e0 + e1;
        sumB += e2 + e3;
    }
    sumA += __shfl_xor_sync(0xffffffffu, sumA, 1);
    sumA += __shfl_xor_sync(0xffffffffu, sumA, 2);
    sumB += __shfl_xor_sync(0xffffffffu, sumB, 1);
    sumB += __shfl_xor_sync(0xffffffffu, sumB, 2);
    const float invA = 1.f / sumA, invB = 1.f / sumB;

    u32 ph[8][2];
    #pragma unroll
    for (int ni = 0; ni < 8; ni++) {
        __half2 lo = __floats2half2_rn(sacc[ni][0] * invA, sacc[ni][1] * invA);
        __half2 hi = __floats2half2_rn(sacc[ni][2] * invB, sacc[ni][3] * invB);
        ph[ni][0] = *(u32*)&lo;
        ph[ni][1] = *(u32*)&hi;
    }

    float oacc[8][4];
    #pragma unroll
    for (int ni = 0; ni < 8; ni++)
        #pragma unroll
        for (int r = 0; r < 4; r++) oacc[ni][r] = 0.f;

    #pragma unroll
    for (int j = 0; j < 4; j++) {
        u32 a0 = ph[2 * j][0], a1 = ph[2 * j][1];
        u32 a2 = ph[2 * j + 1][0], a3 = ph[2 * j + 1][1];
        u32 bfrag[8][2];
        #pragma unroll
        for (int np = 0; np < 4; np++) {
            u32 r0, r1, r2, r3;
            ldsm4t(r0, r1, r2, r3,
                   vsA + voff0 + (u32)((j * 16 * TSTRIDE + np * 16) * 2));
            bfrag[np * 2 + 0][0] = r0; bfrag[np * 2 + 0][1] = r1;
            bfrag[np * 2 + 1][0] = r2; bfrag[np * 2 + 1][1] = r3;
        }
        #pragma unroll
        for (int ni = 0; ni < 8; ni++)
            mma_f16(&oacc[ni][0], a0, a1, a2, a3, bfrag[ni][0], bfrag[ni][1]);
    }

    __half* dA = ctx + (size_t)(rowbase + rowA) * DD + colbase + tig * 2;
    __half* dB = ctx + (size_t)(rowbase + rowB) * DD + colbase + tig * 2;
    #pragma unroll
    for (int ni = 0; ni < 8; ni++) {
        *(__half2*)(dA + ni * 8) = __floats2half2_rn(oacc[ni][0], oacc[ni][1]);
        *(__half2*)(dB + ni * 8) = __floats2half2_rn(oacc[ni][2], oacc[ni][3]);
    }
}

// ---------------- launch ----------------
extern "C" void kernel_launch(void* const* d_in, const int* in_sizes, int n_in,
                              void* d_out, int out_size)
{
    const float* x    = (const float*)d_in[0];
    const float* Wq   = (const float*)d_in[2];
    const float* bq   = (const float*)d_in[3];
    const float* Wk   = (const float*)d_in[4];
    const float* bk   = (const float*)d_in[5];
    const float* Wv   = (const float*)d_in[6];
    const float* bv   = (const float*)d_in[7];
    const float* Wo   = (const float*)d_in[8];
    const float* bo   = (const float*)d_in[9];
    const float* ln1g = (const float*)d_in[10];
    const float* ln1b = (const float*)d_in[11];
    const float* ln2g = (const float*)d_in[12];
    const float* ln2b = (const float*)d_in[13];
    const float* W1   = (const float*)d_in[14];
    const float* b1   = (const float*)d_in[15];
    const float* W2   = (const float*)d_in[16];
    const float* b2   = (const float*)d_in[17];
    float* out = (float*)d_out;

    __half *h, *qkv, *ctx, *ff;
    float *x1, *bqkv;
    __half *wqkv, *wo, *w1, *w2;
    cudaGetSymbolAddress((void**)&h,    g_h);
    cudaGetSymbolAddress((void**)&qkv,  g_qkv);
    cudaGetSymbolAddress((void**)&ctx,  g_ctx);
    cudaGetSymbolAddress((void**)&x1,   g_x1);
    cudaGetSymbolAddress((void**)&ff,   g_ff);
    cudaGetSymbolAddress((void**)&wqkv, g_wqkv);
    cudaGetSymbolAddress((void**)&wo,   g_wo);
    cudaGetSymbolAddress((void**)&w1,   g_w1);
    cudaGetSymbolAddress((void**)&w2,   g_w2);
    cudaGetSymbolAddress((void**)&bqkv, g_bqkv);

    cudaFuncSetAttribute((const void*)mma_gemm<0, DD>,
                         cudaFuncAttributeMaxDynamicSharedMemorySize, SMEM_BYTES);
    cudaFuncSetAttribute((const void*)mma_gemm<2, DD>,
                         cudaFuncAttributeMaxDynamicSharedMemorySize, SMEM_BYTES);
    cudaFuncSetAttribute((const void*)mma_gemm<1, DD>,
                         cudaFuncAttributeMaxDynamicSharedMemorySize, SMEM_BYTES);
    cudaFuncSetAttribute((const void*)mma_gemm<2, DFFN>,
                         cudaFuncAttributeMaxDynamicSharedMemorySize, SMEM_BYTES);

    // fork: cvtB (Wo/W1/W2) runs on a side stream, overlapping cvtA + QKV + attn
    cudaStream_t s1;
    cudaStreamCreateWithFlags(&s1, cudaStreamNonBlocking);
    cudaEvent_t e0, e1;
    cudaEventCreateWithFlags(&e0, cudaEventDisableTiming);
    cudaEventCreateWithFlags(&e1, cudaEventDisableTiming);

    cudaEventRecord(e0, 0);                 // fork point on main (legacy) stream
    cudaStreamWaitEvent(s1, e0, 0);
    cvtB_kernel<<<9216, dim3(32, 8), 0, s1>>>(Wo, W1, W2);
    cudaEventRecord(e1, s1);

    // main stream: cvtA (Wq/k/v + bias + LN1)
    cvtA_kernel<<<3073 + MROWS, dim3(32, 8)>>>(Wq, Wk, Wv, bq, bk, bv, x, ln1g, ln1b);

    // 2. fused QKV projection (K=1024)
    dim3 gQKV(NQKV / 128, MROWS / 128);
    mma_gemm<0, DD><<<gQKV, 128, SMEM_BYTES>>>(h, wqkv, bqkv, nullptr, qkv, NQKV, 0.f);

    // 3. tensor-core attention -> ctx (half)
    dim3 gA(SS / 64, HH, BB);
    attn_kernel<<<gA, 128>>>(qkv, ctx);

    // join: Wo/W1/W2 conversion must be done before step 4
    cudaStreamWaitEvent(0, e1, 0);

    // 4. x1 = x + (ctx @ Wo + bo) * res_scale   (K=1024)
    dim3 gD(DD / 128, MROWS / 128);
    mma_gemm<2, DD><<<gD, 128, SMEM_BYTES>>>(ctx, wo, bo, x, x1, DD, RES_SCALE);

    // 5. LN2 -> h (half)
    ln_kernel<<<MROWS, 256>>>(x1, ln2g, ln2b, h);

    // 6. ff = (half)gelu(h @ W1 + b1)   (K=1024)
    dim3 gF1(DFFN / 128, MROWS / 128);
    mma_gemm<1, DD><<<gF1, 128, SMEM_BYTES>>>(h, w1, b1, nullptr, ff, DFFN, 0.f);

    // 7. out = x1 + (ff @ W2 + b2) * res_scale   (K=4096)
    mma_gemm<2, DFFN><<<gD, 128, SMEM_BYTES>>>(ff, w2, b2, x1, out, DD, RES_SCALE);

    cudaEventDestroy(e0);
    cudaEventDestroy(e1);
    cudaStreamDestroy(s1);
}

// round 16
// speedup vs baseline: 1.0617x; 1.0387x over previous
#include <cuda_runtime.h>
#include <cuda_fp16.h>
#include <math.h>

typedef unsigned int u32;

// Problem constants
#define BB 2
#define SS 2048
#define DD 1024
#define HH 16
#define DFFN 4096
#define MROWS (BB*SS)          // 4096
#define NQKV 3072
#define RES_SCALE 0.70710678118654752440f

// ---------------- device scratch ----------------
__device__ __half g_h   [MROWS * DD];
__device__ __half g_qkv [MROWS * NQKV];
__device__ __half g_ctx [MROWS * DD];
__device__ float  g_x1  [MROWS * DD];
__device__ __half g_ff  [MROWS * DFFN];
__device__ __half g_wqkv[NQKV * DD];
__device__ __half g_wo  [DD * DD];
__device__ __half g_w1  [DFFN * DD];
__device__ __half g_w2  [DD * DFFN];
__device__ float  g_bqkv[NQKV];

// ---------------- fused convert + LN1 (one launch) ----------------
// blocks [0,12288): weight transpose-convert; 12288: bias concat;
// blocks [12289, 12289+4096): LN1 rows (x -> g_h fp16)
__global__ __launch_bounds__(256) void cvt_all_kernel(
    const float* __restrict__ Wq, const float* __restrict__ Wk,
    const float* __restrict__ Wv, const float* __restrict__ Wo,
    const float* __restrict__ W1, const float* __restrict__ W2,
    const float* __restrict__ bq, const float* __restrict__ bk,
    const float* __restrict__ bv,
    const float* __restrict__ x,
    const float* __restrict__ ln1g, const float* __restrict__ ln1b)
{
    int bid = blockIdx.x;
    int tx = threadIdx.x, ty = threadIdx.y;
    int tid = ty * 32 + tx;

    if (bid >= 12289) {
        // ---- LN1 row ----
        int row = bid - 12289;
        const float4* xr = (const float4*)(x + (size_t)row * DD);
        float4 v = xr[tid];
        float s  = v.x + v.y + v.z + v.w;
        float ss = v.x*v.x + v.y*v.y + v.z*v.z + v.w*v.w;
        #pragma unroll
        for (int o = 16; o; o >>= 1) {
            s  += __shfl_xor_sync(0xffffffffu, s, o);
            ss += __shfl_xor_sync(0xffffffffu, ss, o);
        }
        __shared__ float sm1[8], sm2[8];
        int w = tid >> 5, l = tid & 31;
        if (l == 0) { sm1[w] = s; sm2[w] = ss; }
        __syncthreads();
        if (tid == 0) {
            float S = 0.f, SSu = 0.f;
            #pragma unroll
            for (int i = 0; i < 8; i++) { S += sm1[i]; SSu += sm2[i]; }
            float mu  = S  * (1.f / DD);
            float var = SSu * (1.f / DD) - mu * mu;
            sm1[0] = mu;
            sm2[0] = rsqrtf(var + 1e-5f);
        }
        __syncthreads();
        float mu  = sm1[0];
        float inv = sm2[0];
        float4 gg = ((const float4*)ln1g)[tid];
        float4 bb = ((const float4*)ln1b)[tid];
        __half2* orow = (__half2*)(g_h + (size_t)row * DD);
        orow[tid * 2 + 0] = __floats2half2_rn((v.x - mu) * inv * gg.x + bb.x,
                                              (v.y - mu) * inv * gg.y + bb.y);
        orow[tid * 2 + 1] = __floats2half2_rn((v.z - mu) * inv * gg.z + bb.z,
                                              (v.w - mu) * inv * gg.w + bb.w);
        return;
    }

    if (bid == 12288) {
        #pragma unroll
        for (int i = 0; i < 4; i++) {
            int j = tid + i * 256;
            g_bqkv[j]          = bq[j];
            g_bqkv[DD + j]     = bk[j];
            g_bqkv[2 * DD + j] = bv[j];
        }
        return;
    }

    const float* in;
    __half* out;
    int Kdim, Ndim, n0, k0, rowOff;
    if (bid < 4096) {
        int m = bid >> 10;
        int lb = bid & 1023;
        Kdim = DD; Ndim = DD;
        n0 = (lb & 31) * 32; k0 = (lb >> 5) * 32;
        if (m == 0)      { in = Wq; out = g_wqkv; rowOff = 0; }
        else if (m == 1) { in = Wk; out = g_wqkv; rowOff = DD; }
        else if (m == 2) { in = Wv; out = g_wqkv; rowOff = 2 * DD; }
        else             { in = Wo; out = g_wo;   rowOff = 0; }
    } else if (bid < 8192) {
        int lb = bid - 4096;
        Kdim = DD; Ndim = DFFN;
        n0 = (lb & 127) * 32; k0 = (lb >> 7) * 32;
        in = W1; out = g_w1; rowOff = 0;
    } else {
        int lb = bid - 8192;
        Kdim = DFFN; Ndim = DD;
        n0 = (lb & 31) * 32; k0 = (lb >> 5) * 32;
        in = W2; out = g_w2; rowOff = 0;
    }

    __shared__ float sm[32][33];
    #pragma unroll
    for (int i = 0; i < 4; i++) {
        int r = ty + i * 8;
        sm[r][tx] = in[(size_t)(k0 + r) * Ndim + n0 + tx];
    }
    __syncthreads();
    #pragma unroll
    for (int i = 0; i < 4; i++) {
        int r = ty + i * 8;
        out[(size_t)(rowOff + n0 + r) * Kdim + k0 + tx] = __float2half_rn(sm[tx][r]);
    }
}

// ---------------- LayerNorm (fp32 in, fp16 out) — used for LN2 ----------------
__global__ __launch_bounds__(256) void ln_kernel(const float* __restrict__ x,
                                                 const float* __restrict__ g,
                                                 const float* __restrict__ b,
                                                 __half* __restrict__ out)
{
    int row = blockIdx.x;
    int tid = threadIdx.x;
    const float4* xr = (const float4*)(x + (size_t)row * DD);
    float4 v = xr[tid];
    float s  = v.x + v.y + v.z + v.w;
    float ss = v.x*v.x + v.y*v.y + v.z*v.z + v.w*v.w;
    #pragma unroll
    for (int o = 16; o; o >>= 1) {
        s  += __shfl_xor_sync(0xffffffffu, s, o);
        ss += __shfl_xor_sync(0xffffffffu, ss, o);
    }
    __shared__ float sm1[8], sm2[8];
    int w = tid >> 5, l = tid & 31;
    if (l == 0) { sm1[w] = s; sm2[w] = ss; }
    __syncthreads();
    if (tid == 0) {
        float S = 0.f, SSu = 0.f;
        #pragma unroll
        for (int i = 0; i < 8; i++) { S += sm1[i]; SSu += sm2[i]; }
        float mu  = S  * (1.f / DD);
        float var = SSu * (1.f / DD) - mu * mu;
        sm1[0] = mu;
        sm2[0] = rsqrtf(var + 1e-5f);
    }
    __syncthreads();
    float mu  = sm1[0];
    float inv = sm2[0];
    float4 gg = ((const float4*)g)[tid];
    float4 bb = ((const float4*)b)[tid];
    __half2* orow = (__half2*)(out + (size_t)row * DD);
    orow[tid * 2 + 0] = __floats2half2_rn((v.x - mu) * inv * gg.x + bb.x,
                                          (v.y - mu) * inv * gg.y + bb.y);
    orow[tid * 2 + 1] = __floats2half2_rn((v.z - mu) * inv * gg.z + bb.z,
                                          (v.w - mu) * inv * gg.w + bb.w);
}

// ---------------- FP16 tensor-core GEMM (R12 config; HMMA pipe-saturated) ------------
#define BKH 64
#define TSTRIDE 72
#define OP_STAGE (128 * TSTRIDE)
#define NSTAGE 3
#define STAGE_H (2 * OP_STAGE)
#define SMEM_BYTES (NSTAGE * STAGE_H * 2)        // 110592 B

__device__ __forceinline__ float tanh_approx(float x) {
    float y;
    asm("tanh.approx.f32 %0, %1;" : "=f"(y) : "f"(x));
    return y;
}
__device__ __forceinline__ float gelu_tanh(float x) {
    float x3 = x * x * x;
    return 0.5f * x * (1.f + tanh_approx(0.7978845608028654f * (x + 0.044715f * x3)));
}
__device__ __forceinline__ void cp_async16h(__half* dst, const __half* src) {
    u32 d = (u32)__cvta_generic_to_shared(dst);
    asm volatile("cp.async.cg.shared.global [%0], [%1], 16;\n" :: "r"(d), "l"(src));
}
__device__ __forceinline__ void cp_commit() {
    asm volatile("cp.async.commit_group;\n");
}
__device__ __forceinline__ void cp_wait1() {
    asm volatile("cp.async.wait_group 1;\n" ::: "memory");
}
__device__ __forceinline__ void ldsm4(u32& r0, u32& r1, u32& r2, u32& r3, u32 addr) {
    asm volatile("ldmatrix.sync.aligned.m8n8.x4.shared.b16 {%0,%1,%2,%3}, [%4];"
                 : "=r"(r0), "=r"(r1), "=r"(r2), "=r"(r3) : "r"(addr));
}
__device__ __forceinline__ void ldsm4t(u32& r0, u32& r1, u32& r2, u32& r3, u32 addr) {
    asm volatile("ldmatrix.sync.aligned.m8n8.x4.trans.shared.b16 {%0,%1,%2,%3}, [%4];"
                 : "=r"(r0), "=r"(r1), "=r"(r2), "=r"(r3) : "r"(addr));
}
__device__ __forceinline__ void mma_f16(float* acc,
                                        u32 a0, u32 a1, u32 a2, u32 a3,
                                        u32 b0, u32 b1)
{
    float d0 = acc[0], d1 = acc[1], d2 = acc[2], d3 = acc[3];
    asm volatile(
        "mma.sync.aligned.m16n8k16.row.col.f32.f16.f16.f32 "
        "{%0,%1,%2,%3}, {%4,%5,%6,%7}, {%8,%9}, {%0,%1,%2,%3};"
        : "+f"(d0), "+f"(d1), "+f"(d2), "+f"(d3)
        : "r"(a0), "r"(a1), "r"(a2), "r"(a3), "r"(b0), "r"(b1));
    acc[0] = d0; acc[1] = d1; acc[2] = d2; acc[3] = d3;
}

template<int MODE, int KDIM>
__global__ __launch_bounds__(128, 2)
void mma_gemm(const __half* __restrict__ A, const __half* __restrict__ Bt,
              const float* __restrict__ bias, const float* __restrict__ R,
              void* __restrict__ Cv, int N, float scale)
{
    extern __shared__ __half smem[];
    constexpr int K = KDIM;
    constexpr int T = K / BKH;

    const int tid  = threadIdx.x;
    const int lane = tid & 31;
    const int warp = tid >> 5;
    const int wm   = (warp >> 1) * 64;
    const int wn   = (warp & 1) * 64;
    const int bm   = blockIdx.y * 128;
    const int bn   = blockIdx.x * 128;
    const int gid  = lane >> 2;
    const int tig  = lane & 3;

    const int q = lane >> 3, ri = lane & 7;
    const u32 aoff0 = (u32)(((wm + (q & 1) * 8 + ri) * TSTRIDE + (q >> 1) * 8) * 2);
    const u32 boff0 = (u32)(((wn + (q >> 1) * 8 + ri) * TSTRIDE + (q & 1) * 8) * 2);

    float acc[4][8][4];
    #pragma unroll
    for (int mi = 0; mi < 4; mi++)
        #pragma unroll
        for (int ni = 0; ni < 8; ni++)
            #pragma unroll
            for (int r = 0; r < 4; r++) acc[mi][ni][r] = 0.f;

    auto load_tile = [&](int s, int tp) {
        __half* as = smem + s * STAGE_H;
        __half* bs = as + OP_STAGE;
        int k0 = tp * BKH;
        const __half* Ag = A + (size_t)bm * K + k0;
        const __half* Bg = Bt + (size_t)bn * K + k0;
        #pragma unroll
        for (int i = 0; i < 8; i++) {
            int idx = tid + i * 128;
            int r = idx >> 3, c = (idx & 7) * 8;
            cp_async16h(as + r * TSTRIDE + c, Ag + (size_t)r * K + c);
            cp_async16h(bs + r * TSTRIDE + c, Bg + (size_t)r * K + c);
        }
        cp_commit();
    };

    load_tile(0, 0);
    load_tile(1, 1);

    int sc = 0;
    #pragma unroll 2
    for (int t = 0; t < T; t++) {
        cp_wait1();
        __syncthreads();

        if (t + 2 < T) {
            int sp = sc + 2; if (sp >= NSTAGE) sp -= NSTAGE;
            load_tile(sp, t + 2);
        }

        const u32 asAddr = (u32)__cvta_generic_to_shared(smem + sc * STAGE_H);
        const u32 bsAddr = asAddr + (u32)(OP_STAGE * 2);

        u32 af[2][4][4];
        u32 bf[2][8][2];

        #pragma unroll
        for (int mi = 0; mi < 4; mi++) {
            u32 r0, r1, r2, r3;
            ldsm4(r0, r1, r2, r3, asAddr + aoff0 + (u32)(mi * 16 * TSTRIDE * 2));
            af[0][mi][0] = r0; af[0][mi][1] = r1; af[0][mi][2] = r2; af[0][mi][3] = r3;
        }
        #pragma unroll
        for (int np = 0; np < 4; np++) {
            u32 r0, r1, r2, r3;
            ldsm4(r0, r1, r2, r3, bsAddr + boff0 + (u32)(np * 16 * TSTRIDE * 2));
            bf[0][np * 2 + 0][0] = r0; bf[0][np * 2 + 0][1] = r1;
            bf[0][np * 2 + 1][0] = r2; bf[0][np * 2 + 1][1] = r3;
        }

        #pragma unroll
        for (int kk = 0; kk < 4; kk++) {
            const int cb = kk & 1, nb = cb ^ 1;
            if (kk < 3) {
                const u32 kb = (u32)((kk + 1) * 32);
                #pragma unroll
                for (int mi = 0; mi < 4; mi++) {
                    u32 r0, r1, r2, r3;
                    ldsm4(r0, r1, r2, r3, asAddr + aoff0 + (u32)(mi * 16 * TSTRIDE * 2) + kb);
                    af[nb][mi][0] = r0; af[nb][mi][1] = r1;
                    af[nb][mi][2] = r2; af[nb][mi][3] = r3;
                }
                #pragma unroll
                for (int np = 0; np < 4; np++) {
                    u32 r0, r1, r2, r3;
                    ldsm4(r0, r1, r2, r3, bsAddr + boff0 + (u32)(np * 16 * TSTRIDE * 2) + kb);
                    bf[nb][np * 2 + 0][0] = r0; bf[nb][np * 2 + 0][1] = r1;
                    bf[nb][np * 2 + 1][0] = r2; bf[nb][np * 2 + 1][1] = r3;
                }
            }
            #pragma unroll
            for (int mi = 0; mi < 4; mi++) {
                u32 a0 = af[cb][mi][0], a1 = af[cb][mi][1];
                u32 a2 = af[cb][mi][2], a3 = af[cb][mi][3];
                #pragma unroll
                for (int ni = 0; ni < 8; ni++) {
                    u32 b0 = bf[cb][ni][0], b1 = bf[cb][ni][1];
                    mma_f16(&acc[mi][ni][0], a0, a1, a2, a3, b0, b1);
                }
            }
        }

        if (++sc >= NSTAGE) sc = 0;
    }

    const int rbase = bm + wm + gid;
    const int cbase = bn + wn + tig * 2;
    #pragma unroll
    for (int mi = 0; mi < 4; mi++) {
        #pragma unroll
        for (int half_ = 0; half_ < 2; half_++) {
            int r = rbase + mi * 16 + half_ * 8;
            #pragma unroll
            for (int ni = 0; ni < 8; ni++) {
                int c = cbase + ni * 8;
                float v0 = acc[mi][ni][half_ * 2 + 0] + bias[c];
                float v1 = acc[mi][ni][half_ * 2 + 1] + bias[c + 1];
                if (MODE == 0) {
                    __half2* C = (__half2*)((__half*)Cv + (size_t)r * N + c);
                    *C = __floats2half2_rn(v0, v1);
                } else if (MODE == 1) {
                    __half2* C = (__half2*)((__half*)Cv + (size_t)r * N + c);
                    *C = __floats2half2_rn(gelu_tanh(v0), gelu_tanh(v1));
                } else {
                    float* C = (float*)Cv + (size_t)r * N + c;
                    const float2 rr = *(const float2*)(R + (size_t)r * N + c);
                    float2 o2;
                    o2.x = rr.x + v0 * scale;
                    o2.y = rr.y + v1 * scale;
                    *(float2*)C = o2;
                }
            }
        }
    }
}

// ---------------- tensor-core block-local causal attention ----------------
__global__ __launch_bounds__(128)
void attn_kernel(const __half* __restrict__ qkv, __half* __restrict__ ctx)
{
    __shared__ __half qs[64 * TSTRIDE];
    __shared__ __half ks[64 * TSTRIDE];
    __shared__ __half vs[64 * TSTRIDE];

    const int tid  = threadIdx.x;
    const int lane = tid & 31;
    const int warp = tid >> 5;
    const int gid  = lane >> 2;
    const int tig  = lane & 3;
    const int rowbase = blockIdx.z * SS + blockIdx.x * 64;
    const int colbase = blockIdx.y * 64;

    #pragma unroll
    for (int i = 0; i < 4; i++) {
        int idx = tid + i * 128;
        int r = idx >> 3, c = (idx & 7) * 8;
        size_t base = (size_t)(rowbase + r) * NQKV + colbase + c;
        *(uint4*)(qs + r * TSTRIDE + c) = *(const uint4*)(qkv + base);
        *(uint4*)(ks + r * TSTRIDE + c) = *(const uint4*)(qkv + base + DD);
        *(uint4*)(vs + r * TSTRIDE + c) = *(const uint4*)(qkv + base + 2 * DD);
    }
    __syncthreads();

    const int q = lane >> 3, ri = lane & 7;
    const u32 qsA = (u32)__cvta_generic_to_shared(qs);
    const u32 ksA = (u32)__cvta_generic_to_shared(ks);
    const u32 vsA = (u32)__cvta_generic_to_shared(vs);
    const u32 aoff0 = (u32)(((warp * 16 + (q & 1) * 8 + ri) * TSTRIDE + (q >> 1) * 8) * 2);
    const u32 boff0 = (u32)((((q >> 1) * 8 + ri) * TSTRIDE + (q & 1) * 8) * 2);
    const u32 voff0 = (u32)((((q & 1) * 8 + ri) * TSTRIDE + (q >> 1) * 8) * 2);

    float sacc[8][4];
    #pragma unroll
    for (int ni = 0; ni < 8; ni++)
        #pragma unroll
        for (int r = 0; r < 4; r++) sacc[ni][r] = 0.f;

    #pragma unroll
    for (int j = 0; j < 4; j++) {
        const u32 kb = (u32)(j * 32);
        u32 a0, a1, a2, a3;
        ldsm4(a0, a1, a2, a3, qsA + aoff0 + kb);
        u32 bfrag[8][2];
        #pragma unroll
        for (int np = 0; np < 4; np++) {
            u32 r0, r1, r2, r3;
            ldsm4(r0, r1, r2, r3, ksA + boff0 + (u32)(np * 16 * TSTRIDE * 2) + kb);
            bfrag[np * 2 + 0][0] = r0; bfrag[np * 2 + 0][1] = r1;
            bfrag[np * 2 + 1][0] = r2; bfrag[np * 2 + 1][1] = r3;
        }
        #pragma unroll
        for (int ni = 0; ni < 8; ni++)
            mma_f16(&sacc[ni][0], a0, a1, a2, a3, bfrag[ni][0], bfrag[ni][1]);
    }

    const int rowA = warp * 16 + gid;
    const int rowB = rowA + 8;
    float mA = -1e30f, mB = -1e30f;
    #pragma unroll
    for (int ni = 0; ni < 8; ni++) {
        int c0 = ni * 8 + tig * 2, c1 = c0 + 1;
        float s0 = sacc[ni][0] * 0.125f;
        float s1 = sacc[ni][1] * 0.125f;
        float s2 = sacc[ni][2] * 0.125f;
        float s3 = sacc[ni][3] * 0.125f;
        sacc[ni][0] = s0; sacc[ni][1] = s1; sacc[ni][2] = s2; sacc[ni][3] = s3;
        if (c0 <= rowA) mA = fmaxf(mA, s0);
        if (c1 <= rowA) mA = fmaxf(mA, s1);
        if (c0 <= rowB) mB = fmaxf(mB, s2);
        if (c1 <= rowB) mB = fmaxf(mB, s3);
    }
    mA = fmaxf(mA, __shfl_xor_sync(0xffffffffu, mA, 1));
    mA = fmaxf(mA, __shfl_xor_sync(0xffffffffu, mA, 2));
    mB = fmaxf(mB, __shfl_xor_sync(0xffffffffu, mB, 1));
    mB = fmaxf(mB, __shfl_xor_sync(0xffffffffu, mB, 2));

    float sumA = 0.f, sumB = 0.f;
    #pragma unroll
    for (int ni = 0; ni < 8; ni++) {
        int c0 = ni * 8 + tig * 2, c1 = c0 + 1;
        float e0 = (c0 <= rowA) ? expf(sacc[ni][0] - mA) : 0.f;
        float e1 = (c1 <= rowA) ? expf(sacc[ni][1] - mA) : 0.f;
        float e2 = (c0 <= rowB) ? expf(sacc[ni][2] - mB) : 0.f;
        float e3 = (c1 <= rowB) ? expf(sacc[ni][3] - mB) : 0.f;
        sacc[ni][0] = e0; sacc[ni][1] = e1; sacc[ni][2] = e2; sacc[ni][3] = e3;
        sumA += e0 + e1;
        sumB += e2 + e3;
    }
    sumA += __shfl_xor_sync(0xffffffffu, sumA, 1);
    sumA += __shfl_xor_sync(0xffffffffu, sumA, 2);
    sumB += __shfl_xor_sync(0xffffffffu, sumB, 1);
    sumB += __shfl_xor_sync(0xffffffffu, sumB, 2);
    const float invA = 1.f / sumA, invB = 1.f / sumB;

    u32 ph[8][2];
    #pragma unroll
    for (int ni = 0; ni < 8; ni++) {
        __half2 lo = __floats2half2_rn(sacc[ni][0] * invA, sacc[ni][1] * invA);
        __half2 hi = __floats2half2_rn(sacc[ni][2] * invB, sacc[ni][3] * invB);
        ph[ni][0] = *(u32*)&lo;
        ph[ni][1] = *(u32*)&hi;
    }

    float oacc[8][4];
    #pragma unroll
    for (int ni = 0; ni < 8; ni++)
        #pragma unroll
        for (int r = 0; r < 4; r++) oacc[ni][r] = 0.f;

    #pragma unroll
    for (int j = 0; j < 4; j++) {
        u32 a0 = ph[2 * j][0], a1 = ph[2 * j][1];
        u32 a2 = ph[2 * j + 1][0], a3 = ph[2 * j + 1][1];
        u32 bfrag[8][2];
        #pragma unroll
        for (int np = 0; np < 4; np++) {
            u32 r0, r1, r2, r3;
            ldsm4t(r0, r1, r2, r3,
                   vsA + voff0 + (u32)((j * 16 * TSTRIDE + np * 16) * 2));
            bfrag[np * 2 + 0][0] = r0; bfrag[np * 2 + 0][1] = r1;
            bfrag[np * 2 + 1][0] = r2; bfrag[np * 2 + 1][1] = r3;
        }
        #pragma unroll
        for (int ni = 0; ni < 8; ni++)
            mma_f16(&oacc[ni][0], a0, a1, a2, a3, bfrag[ni][0], bfrag[ni][1]);
    }

    __half* dA = ctx + (size_t)(rowbase + rowA) * DD + colbase + tig * 2;
    __half* dB = ctx + (size_t)(rowbase + rowB) * DD + colbase + tig * 2;
    #pragma unroll
    for (int ni = 0; ni < 8; ni++) {
        *(__half2*)(dA + ni * 8) = __floats2half2_rn(oacc[ni][0], oacc[ni][1]);
        *(__half2*)(dB + ni * 8) = __floats2half2_rn(oacc[ni][2], oacc[ni][3]);
    }
}

// ---------------- launch ----------------
extern "C" void kernel_launch(void* const* d_in, const int* in_sizes, int n_in,
                              void* d_out, int out_size)
{
    const float* x    = (const float*)d_in[0];
    const float* Wq   = (const float*)d_in[2];
    const float* bq   = (const float*)d_in[3];
    const float* Wk   = (const float*)d_in[4];
    const float* bk   = (const float*)d_in[5];
    const float* Wv   = (const float*)d_in[6];
    const float* bv   = (const float*)d_in[7];
    const float* Wo   = (const float*)d_in[8];
    const float* bo   = (const float*)d_in[9];
    const float* ln1g = (const float*)d_in[10];
    const float* ln1b = (const float*)d_in[11];
    const float* ln2g = (const float*)d_in[12];
    const float* ln2b = (const float*)d_in[13];
    const float* W1   = (const float*)d_in[14];
    const float* b1   = (const float*)d_in[15];
    const float* W2   = (const float*)d_in[16];
    const float* b2   = (const float*)d_in[17];
    float* out = (float*)d_out;

    __half *h, *qkv, *ctx, *ff;
    float *x1, *bqkv;
    __half *wqkv, *wo, *w1, *w2;
    cudaGetSymbolAddress((void**)&h,    g_h);
    cudaGetSymbolAddress((void**)&qkv,  g_qkv);
    cudaGetSymbolAddress((void**)&ctx,  g_ctx);
    cudaGetSymbolAddress((void**)&x1,   g_x1);
    cudaGetSymbolAddress((void**)&ff,   g_ff);
    cudaGetSymbolAddress((void**)&wqkv, g_wqkv);
    cudaGetSymbolAddress((void**)&wo,   g_wo);
    cudaGetSymbolAddress((void**)&w1,   g_w1);
    cudaGetSymbolAddress((void**)&w2,   g_w2);
    cudaGetSymbolAddress((void**)&bqkv, g_bqkv);

    cudaFuncSetAttribute((const void*)mma_gemm<0, DD>,
                         cudaFuncAttributeMaxDynamicSharedMemorySize, SMEM_BYTES);
    cudaFuncSetAttribute((const void*)mma_gemm<2, DD>,
                         cudaFuncAttributeMaxDynamicSharedMemorySize, SMEM_BYTES);
    cudaFuncSetAttribute((const void*)mma_gemm<1, DD>,
                         cudaFuncAttributeMaxDynamicSharedMemorySize, SMEM_BYTES);
    cudaFuncSetAttribute((const void*)mma_gemm<2, DFFN>,
                         cudaFuncAttributeMaxDynamicSharedMemorySize, SMEM_BYTES);

    // 0+1. fused convert + LN1 (one launch)
    cvt_all_kernel<<<12289 + MROWS, dim3(32, 8)>>>(Wq, Wk, Wv, Wo, W1, W2,
                                                   bq, bk, bv, x, ln1g, ln1b);

    // 2. fused QKV projection (K=1024)
    dim3 gQKV(NQKV / 128, MROWS / 128);
    mma_gemm<0, DD><<<gQKV, 128, SMEM_BYTES>>>(h, wqkv, bqkv, nullptr, qkv, NQKV, 0.f);

    // 3. tensor-core attention -> ctx (half)
    dim3 gA(SS / 64, HH, BB);
    attn_kernel<<<gA, 128>>>(qkv, ctx);

    // 4. x1 = x + (ctx @ Wo + bo) * res_scale   (K=1024)
    dim3 gD(DD / 128, MROWS / 128);
    mma_gemm<2, DD><<<gD, 128, SMEM_BYTES>>>(ctx, wo, bo, x, x1, DD, RES_SCALE);

    // 5. LN2 -> h (half)
    ln_kernel<<<MROWS, 256>>>(x1, ln2g, ln2b, h);

    // 6. ff = (half)gelu(h @ W1 + b1)   (K=1024)
    dim3 gF1(DFFN / 128, MROWS / 128);
    mma_gemm<1, DD><<<gF1, 128, SMEM_BYTES>>>(h, w1, b1, nullptr, ff, DFFN, 0.f);

    // 7. out = x1 + (ff @ W2 + b2) * res_scale   (K=4096)
    mma_gemm<2, DFFN><<<gD, 128, SMEM_BYTES>>>(ff, w2, b2, x1, out, DD, RES_SCALE);
}